// round 4
// baseline (speedup 1.0000x reference)
#include <cuda_runtime.h>
#include <cuda_bf16.h>
#include <cuda_fp16.h>
#include <math.h>
#include <stdint.h>

// Problem constants
#define BB    2
#define TT    2048
#define CC    512
#define HH    8
#define DD    64
#define C3    1536
#define KSEL  4
#define GAMMA_F 2.5f
#define RHO_F   0.085f
#define TAUCLIP 5.0f
#define NROW  (BB*TT)       // 4096
#define KTOT  512

// ---------------- scratch (device globals) ---------------------------------
__device__ float g_qkv[(size_t)NROW * C3];        // 24 MB fp32
__device__ int   g_idx[NROW * KSEL];
__device__ float g_sig[NROW * KSEL];
__device__ float g_rowsum[NROW];
__device__ float g_invden[NROW];
// QKV GEMM operands (bf16 3-term)
__device__ __nv_bfloat16 g_a_hi[(size_t)NROW * KTOT];
__device__ __nv_bfloat16 g_a_lo[(size_t)NROW * KTOT];
__device__ __nv_bfloat16 g_wt_hi[(size_t)C3 * KTOT];   // Wqkv^T
__device__ __nv_bfloat16 g_wt_lo[(size_t)C3 * KTOT];
// proj GEMM operands (fp16 2-term)
__device__ __half g_ao_h[(size_t)NROW * KTOT];
__device__ __half g_ao_l[(size_t)NROW * KTOT];
__device__ __half g_wp_h[(size_t)CC * KTOT];           // Wproj^T fp16

// ===================== helpers ==============================================
__device__ __forceinline__ uint32_t smem_u32(const void* p) {
    uint32_t a;
    asm("{ .reg .u64 t; cvta.to.shared.u64 t, %1; cvt.u32.u64 %0, t; }" : "=r"(a) : "l"(p));
    return a;
}
__device__ __forceinline__ void ldsm_x4(uint32_t& r0, uint32_t& r1, uint32_t& r2, uint32_t& r3,
                                        uint32_t addr) {
    asm volatile("ldmatrix.sync.aligned.m8n8.x4.shared.b16 {%0,%1,%2,%3}, [%4];"
                 : "=r"(r0), "=r"(r1), "=r"(r2), "=r"(r3) : "r"(addr));
}
__device__ __forceinline__ void mma_bf16(float* d, const uint32_t* a, uint32_t b0, uint32_t b1) {
    asm volatile("mma.sync.aligned.m16n8k16.row.col.f32.bf16.bf16.f32 "
                 "{%0,%1,%2,%3}, {%4,%5,%6,%7}, {%8,%9}, {%0,%1,%2,%3};"
                 : "+f"(d[0]), "+f"(d[1]), "+f"(d[2]), "+f"(d[3])
                 : "r"(a[0]), "r"(a[1]), "r"(a[2]), "r"(a[3]), "r"(b0), "r"(b1));
}
__device__ __forceinline__ void mma_fp16(float* d, const uint32_t* a, uint32_t b0, uint32_t b1) {
    asm volatile("mma.sync.aligned.m16n8k16.row.col.f32.f16.f16.f32 "
                 "{%0,%1,%2,%3}, {%4,%5,%6,%7}, {%8,%9}, {%0,%1,%2,%3};"
                 : "+f"(d[0]), "+f"(d[1]), "+f"(d[2]), "+f"(d[3])
                 : "r"(a[0]), "r"(a[1]), "r"(a[2]), "r"(a[3]), "r"(b0), "r"(b1));
}

// ===================== top-K + rowsum per tau row ===========================
__global__ void topk_kernel(const float* __restrict__ tau) {
    const int row = blockIdx.x;
    const float* tr = tau + (size_t)row * TT;
    __shared__ float sv[TT];
    __shared__ float red[256];
    __shared__ int   redi[256];
    const int tid = threadIdx.x;

    float sum = 0.f;
    #pragma unroll
    for (int i = tid; i < TT; i += 256) { float v = tr[i]; sv[i] = v; sum += v; }
    red[tid] = sum; __syncthreads();
    for (int s = 128; s > 0; s >>= 1) {
        if (tid < s) red[tid] += red[tid + s];
        __syncthreads();
    }
    if (tid == 0) g_rowsum[row] = red[0];
    __syncthreads();

    for (int pass = 0; pass < KSEL; pass++) {
        float bv = -1e30f; int bi = TT;
        for (int i = tid; i < TT; i += 256) {
            float v = sv[i];
            if (v > bv || (v == bv && i < bi)) { bv = v; bi = i; }
        }
        red[tid] = bv; redi[tid] = bi; __syncthreads();
        for (int s = 128; s > 0; s >>= 1) {
            if (tid < s) {
                float ov = red[tid + s]; int oi = redi[tid + s];
                if (ov > red[tid] || (ov == red[tid] && oi < redi[tid])) {
                    red[tid] = ov; redi[tid] = oi;
                }
            }
            __syncthreads();
        }
        if (tid == 0) { g_idx[row * KSEL + pass] = redi[0]; sv[redi[0]] = -1e30f; }
        __syncthreads();
    }
}

// ===================== operand prep =========================================
__global__ void convert_split(const float* __restrict__ in,
                              __nv_bfloat16* __restrict__ hi,
                              __nv_bfloat16* __restrict__ lo, int n) {
    int i = blockIdx.x * 256 + threadIdx.x;
    if (i < n) {
        float v = in[i];
        __nv_bfloat16 h = __float2bfloat16(v);
        hi[i] = h;
        lo[i] = __float2bfloat16(v - __bfloat162float(h));
    }
}

// W [K,N] fp32 -> hi/lo [N,K] bf16
__global__ void transpose_split(const float* __restrict__ W,
                                __nv_bfloat16* __restrict__ hi,
                                __nv_bfloat16* __restrict__ lo, int K, int N) {
    __shared__ float tile[32][33];
    int n0 = blockIdx.x * 32, k0 = blockIdx.y * 32;
    int tx = threadIdx.x, ty = threadIdx.y;
    #pragma unroll
    for (int i = 0; i < 32; i += 8)
        tile[ty + i][tx] = W[(size_t)(k0 + ty + i) * N + n0 + tx];
    __syncthreads();
    #pragma unroll
    for (int i = 0; i < 32; i += 8) {
        float v = tile[tx][ty + i];
        __nv_bfloat16 h = __float2bfloat16(v);
        size_t o = (size_t)(n0 + ty + i) * K + k0 + tx;
        hi[o] = h;
        lo[o] = __float2bfloat16(v - __bfloat162float(h));
    }
}

// W [K,N] fp32 -> [N,K] fp16 (single)
__global__ void transpose_half(const float* __restrict__ W,
                               __half* __restrict__ out, int K, int N) {
    __shared__ float tile[32][33];
    int n0 = blockIdx.x * 32, k0 = blockIdx.y * 32;
    int tx = threadIdx.x, ty = threadIdx.y;
    #pragma unroll
    for (int i = 0; i < 32; i += 8)
        tile[ty + i][tx] = W[(size_t)(k0 + ty + i) * N + n0 + tx];
    __syncthreads();
    #pragma unroll
    for (int i = 0; i < 32; i += 8)
        out[(size_t)(n0 + ty + i) * K + k0 + tx] = __float2half(tile[tx][ty + i]);
}

// ===================== QKV GEMM: bf16 3-term, 256x128 block =================
// C[M,N] = A[M,512]*B^T + bias.  8 warps (4m x 2n), warp tile 64x64.
#define GBK 32
#define NCHUNK (KTOT / GBK)          // 16
#define RPB 80                       // bytes per padded smem row (40 elems)
#define QA_TILE (256 * RPB)          // 20480
#define QB_TILE (128 * RPB)          // 10240
#define QSTAGE (2*QA_TILE + 2*QB_TILE)  // 61440
#define QNST 3
#define QKV_SMEM (QNST * QSTAGE)     // 184320

__device__ __forceinline__ void qkv_load_chunk(
    uint32_t sm_base, int stage, int c, int m0, int n0, int tid,
    const __nv_bfloat16* __restrict__ Ahi, const __nv_bfloat16* __restrict__ Alo,
    const __nv_bfloat16* __restrict__ Bhi, const __nv_bfloat16* __restrict__ Blo)
{
    if (c < NCHUNK) {
        uint32_t sbase = sm_base + stage * QSTAGE;
        const int k0 = c * GBK;
        const __nv_bfloat16* asrc[2] = {Ahi, Alo};
        #pragma unroll
        for (int t = 0; t < 2; t++) {
            #pragma unroll
            for (int i = 0; i < 4; i++) {
                int u = tid + i * 256;           // 0..1023
                int row = u >> 2, c16 = u & 3;
                const void* gp = asrc[t] + (size_t)(m0 + row) * KTOT + k0 + c16 * 8;
                uint32_t dst = sbase + t * QA_TILE + row * RPB + c16 * 16;
                asm volatile("cp.async.cg.shared.global [%0], [%1], 16;" :: "r"(dst), "l"(gp));
            }
        }
        const __nv_bfloat16* bsrc[2] = {Bhi, Blo};
        #pragma unroll
        for (int t = 0; t < 2; t++) {
            #pragma unroll
            for (int i = 0; i < 2; i++) {
                int u = tid + i * 256;           // 0..511
                int row = u >> 2, c16 = u & 3;
                const void* gp = bsrc[t] + (size_t)(n0 + row) * KTOT + k0 + c16 * 8;
                uint32_t dst = sbase + 2 * QA_TILE + t * QB_TILE + row * RPB + c16 * 16;
                asm volatile("cp.async.cg.shared.global [%0], [%1], 16;" :: "r"(dst), "l"(gp));
            }
        }
    }
    asm volatile("cp.async.commit_group;" ::: "memory");
}

__global__ __launch_bounds__(256) void qkv_gemm(
    const __nv_bfloat16* __restrict__ Ahi, const __nv_bfloat16* __restrict__ Alo,
    const __nv_bfloat16* __restrict__ Bhi, const __nv_bfloat16* __restrict__ Blo,
    const float* __restrict__ bias, float* __restrict__ Cout, int N)
{
    extern __shared__ char smem[];
    const uint32_t sm_base = smem_u32(smem);
    const int tid = threadIdx.x;
    const int wid = tid >> 5, lane = tid & 31;
    const int wm = wid >> 1, wn = wid & 1;       // 4 x 2
    const int m0 = blockIdx.y * 256;
    const int n0 = blockIdx.x * 128;

    float acc[4][8][4];
    #pragma unroll
    for (int i = 0; i < 4; i++)
        #pragma unroll
        for (int j = 0; j < 8; j++)
            #pragma unroll
            for (int l = 0; l < 4; l++) acc[i][j][l] = 0.f;

    qkv_load_chunk(sm_base, 0, 0, m0, n0, tid, Ahi, Alo, Bhi, Blo);
    qkv_load_chunk(sm_base, 1, 1, m0, n0, tid, Ahi, Alo, Bhi, Blo);

    const int lrow = lane & 15;
    const int lcol = (lane >> 4) << 3;

    for (int c = 0; c < NCHUNK; c++) {
        asm volatile("cp.async.wait_group 1;" ::: "memory");
        __syncthreads();
        qkv_load_chunk(sm_base, (c + 2) % QNST, c + 2, m0, n0, tid, Ahi, Alo, Bhi, Blo);

        const uint32_t stg = sm_base + (c % QNST) * QSTAGE;
        #pragma unroll
        for (int kk = 0; kk < 2; kk++) {
            const int kc = kk * 16 + lcol;
            uint32_t ah[4][4], al[4][4];
            #pragma unroll
            for (int im = 0; im < 4; im++) {
                uint32_t ra = (wm * 64 + im * 16 + lrow) * RPB + kc * 2;
                ldsm_x4(ah[im][0], ah[im][1], ah[im][2], ah[im][3], stg + ra);
                ldsm_x4(al[im][0], al[im][1], al[im][2], al[im][3], stg + QA_TILE + ra);
            }
            #pragma unroll
            for (int jn = 0; jn < 4; jn++) {
                uint32_t rb = (wn * 64 + jn * 16 + lrow) * RPB + kc * 2;
                uint32_t bh[4], bl[4];
                ldsm_x4(bh[0], bh[1], bh[2], bh[3], stg + 2 * QA_TILE + rb);
                ldsm_x4(bl[0], bl[1], bl[2], bl[3], stg + 2 * QA_TILE + QB_TILE + rb);
                #pragma unroll
                for (int im = 0; im < 4; im++) {
                    mma_bf16(acc[im][jn * 2],     ah[im], bh[0], bh[2]);
                    mma_bf16(acc[im][jn * 2],     ah[im], bl[0], bl[2]);
                    mma_bf16(acc[im][jn * 2],     al[im], bh[0], bh[2]);
                    mma_bf16(acc[im][jn * 2 + 1], ah[im], bh[1], bh[3]);
                    mma_bf16(acc[im][jn * 2 + 1], ah[im], bl[1], bl[3]);
                    mma_bf16(acc[im][jn * 2 + 1], al[im], bh[1], bh[3]);
                }
            }
        }
    }

    #pragma unroll
    for (int im = 0; im < 4; im++) {
        int rbase = m0 + wm * 64 + im * 16 + (lane >> 2);
        #pragma unroll
        for (int jf = 0; jf < 8; jf++) {
            int col = n0 + wn * 64 + jf * 8 + (lane & 3) * 2;
            float2 b2 = *reinterpret_cast<const float2*>(bias + col);
            float2 o0, o1;
            o0.x = acc[im][jf][0] + b2.x; o0.y = acc[im][jf][1] + b2.y;
            o1.x = acc[im][jf][2] + b2.x; o1.y = acc[im][jf][3] + b2.y;
            *reinterpret_cast<float2*>(Cout + (size_t)rbase * N + col) = o0;
            *reinterpret_cast<float2*>(Cout + (size_t)(rbase + 8) * N + col) = o1;
        }
    }
}

// ===================== proj GEMM: fp16 2-term, 128x128 block ================
#define PT_TILE (128 * RPB)          // 10240
#define PSTAGE (3 * PT_TILE)         // Ah, Al, Bh = 30720
#define PNST 3
#define PROJ_SMEM (PNST * PSTAGE)    // 92160

__device__ __forceinline__ void proj_load_chunk(
    uint32_t sm_base, int stage, int c, int m0, int n0, int tid,
    const __half* __restrict__ Ah, const __half* __restrict__ Al,
    const __half* __restrict__ Bh)
{
    if (c < NCHUNK) {
        uint32_t sbase = sm_base + stage * PSTAGE;
        const int k0 = c * GBK;
        const __half* srcs[3] = {Ah, Al, Bh};
        #pragma unroll
        for (int t = 0; t < 3; t++) {
            const int rowbase = (t < 2) ? m0 : n0;
            #pragma unroll
            for (int i = 0; i < 2; i++) {
                int u = tid + i * 256;           // 0..511
                int row = u >> 2, c16 = u & 3;
                const void* gp = srcs[t] + (size_t)(rowbase + row) * KTOT + k0 + c16 * 8;
                uint32_t dst = sbase + t * PT_TILE + row * RPB + c16 * 16;
                asm volatile("cp.async.cg.shared.global [%0], [%1], 16;" :: "r"(dst), "l"(gp));
            }
        }
    }
    asm volatile("cp.async.commit_group;" ::: "memory");
}

__global__ __launch_bounds__(256) void proj_gemm(
    const __half* __restrict__ Ah, const __half* __restrict__ Al,
    const __half* __restrict__ Bh,
    const float* __restrict__ bias, float* __restrict__ Cout, int N)
{
    extern __shared__ char smem[];
    const uint32_t sm_base = smem_u32(smem);
    const int tid = threadIdx.x;
    const int wid = tid >> 5, lane = tid & 31;
    const int wm = wid >> 1, wn = wid & 1;
    const int m0 = blockIdx.y * 128;
    const int n0 = blockIdx.x * 128;

    float acc[2][8][4];
    #pragma unroll
    for (int i = 0; i < 2; i++)
        #pragma unroll
        for (int j = 0; j < 8; j++)
            #pragma unroll
            for (int l = 0; l < 4; l++) acc[i][j][l] = 0.f;

    proj_load_chunk(sm_base, 0, 0, m0, n0, tid, Ah, Al, Bh);
    proj_load_chunk(sm_base, 1, 1, m0, n0, tid, Ah, Al, Bh);

    const int lrow = lane & 15;
    const int lcol = (lane >> 4) << 3;

    for (int c = 0; c < NCHUNK; c++) {
        asm volatile("cp.async.wait_group 1;" ::: "memory");
        __syncthreads();
        proj_load_chunk(sm_base, (c + 2) % PNST, c + 2, m0, n0, tid, Ah, Al, Bh);

        const uint32_t stg = sm_base + (c % PNST) * PSTAGE;
        #pragma unroll
        for (int kk = 0; kk < 2; kk++) {
            const int kc = kk * 16 + lcol;
            uint32_t a_h[2][4], a_l[2][4];
            #pragma unroll
            for (int im = 0; im < 2; im++) {
                uint32_t ra = (wm * 32 + im * 16 + lrow) * RPB + kc * 2;
                ldsm_x4(a_h[im][0], a_h[im][1], a_h[im][2], a_h[im][3], stg + ra);
                ldsm_x4(a_l[im][0], a_l[im][1], a_l[im][2], a_l[im][3], stg + PT_TILE + ra);
            }
            #pragma unroll
            for (int jn = 0; jn < 4; jn++) {
                uint32_t rb = (wn * 64 + jn * 16 + lrow) * RPB + kc * 2;
                uint32_t bh[4];
                ldsm_x4(bh[0], bh[1], bh[2], bh[3], stg + 2 * PT_TILE + rb);
                #pragma unroll
                for (int im = 0; im < 2; im++) {
                    mma_fp16(acc[im][jn * 2],     a_h[im], bh[0], bh[2]);
                    mma_fp16(acc[im][jn * 2],     a_l[im], bh[0], bh[2]);
                    mma_fp16(acc[im][jn * 2 + 1], a_h[im], bh[1], bh[3]);
                    mma_fp16(acc[im][jn * 2 + 1], a_l[im], bh[1], bh[3]);
                }
            }
        }
    }

    #pragma unroll
    for (int im = 0; im < 2; im++) {
        int rbase = m0 + wm * 32 + im * 16 + (lane >> 2);
        #pragma unroll
        for (int jf = 0; jf < 8; jf++) {
            int col = n0 + wn * 64 + jf * 8 + (lane & 3) * 2;
            float2 b2 = *reinterpret_cast<const float2*>(bias + col);
            float2 o0, o1;
            o0.x = acc[im][jf][0] + b2.x; o0.y = acc[im][jf][1] + b2.y;
            o1.x = acc[im][jf][2] + b2.x; o1.y = acc[im][jf][3] + b2.y;
            *reinterpret_cast<float2*>(Cout + (size_t)rbase * N + col) = o0;
            *reinterpret_cast<float2*>(Cout + (size_t)(rbase + 8) * N + col) = o1;
        }
    }
}

// ===================== sparse attention =====================================
__global__ __launch_bounds__(256) void attn_kernel(const float* __restrict__ tau) {
    const int row = blockIdx.x;
    const int tid = threadIdx.x;
    const int warp = tid >> 5, lane = tid & 31;   // warp == head
    const int b = row / TT;

    __shared__ int   sidx[KSEL];
    __shared__ float sbias[KSEL];
    __shared__ float ssig[KSEL];

    if (tid < KSEL) {
        int id = g_idx[row * KSEL + tid];
        sidx[tid]  = id;
        sbias[tid] = GAMMA_F * logf(tau[(size_t)row * TT + id] + 1e-8f);
        ssig[tid]  = 0.f;
    }
    __syncthreads();

    const float* qp = g_qkv + (size_t)row * C3 + warp * DD;
    const float q0 = qp[lane], q1 = qp[lane + 32];

    float logit[KSEL];
    #pragma unroll
    for (int j = 0; j < KSEL; j++) {
        int s = sidx[j];
        const float* kp = g_qkv + (size_t)(b * TT + s) * C3 + CC + warp * DD;
        float p = q0 * kp[lane] + q1 * kp[lane + 32];
        #pragma unroll
        for (int o = 16; o > 0; o >>= 1) p += __shfl_xor_sync(0xffffffffu, p, o);
        logit[j] = p * 0.125f + sbias[j];
    }
    float m = fmaxf(fmaxf(logit[0], logit[1]), fmaxf(logit[2], logit[3]));
    float e[KSEL], se = 0.f;
    #pragma unroll
    for (int j = 0; j < KSEL; j++) { e[j] = expf(logit[j] - m); se += e[j]; }
    float inv = 1.f / se;
    float w[KSEL];
    #pragma unroll
    for (int j = 0; j < KSEL; j++) w[j] = e[j] * inv;

    float o0 = 0.f, o1 = 0.f;
    #pragma unroll
    for (int j = 0; j < KSEL; j++) {
        const float* vp = g_qkv + (size_t)(b * TT + sidx[j]) * C3 + 2 * CC + warp * DD;
        o0 = fmaf(w[j], vp[lane], o0);
        o1 = fmaf(w[j], vp[lane + 32], o1);
    }
    // write attn_out directly as fp16 hi/lo (proj GEMM operand)
    size_t obase = (size_t)row * KTOT + warp * DD;
    __half h0 = __float2half(o0);
    __half h1 = __float2half(o1);
    g_ao_h[obase + lane]      = h0;
    g_ao_h[obase + lane + 32] = h1;
    g_ao_l[obase + lane]      = __float2half(o0 - __half2float(h0));
    g_ao_l[obase + lane + 32] = __float2half(o1 - __half2float(h1));

    if (lane == 0) {
        #pragma unroll
        for (int j = 0; j < KSEL; j++) atomicAdd(&ssig[j], w[j] * (1.0f / HH));
    }
    __syncthreads();
    if (tid == 0) {
        float rs = g_rowsum[row] * (1.0f - RHO_F);
        #pragma unroll
        for (int j = 0; j < KSEL; j++) {
            float s = ssig[j];
            g_sig[row * KSEL + j] = s;
            rs += s * s * s;
        }
        g_invden[row] = 1.f / (rs + 1e-8f);
    }
}

// ===================== tau_new passes =======================================
__global__ void tau_scale(const float* __restrict__ tau, float* __restrict__ out) {
    size_t i = (size_t)blockIdx.x * 256 + threadIdx.x;
    const int row = (int)(i / (TT / 4));
    const float f = (1.0f - RHO_F) * g_invden[row];
    float4 v = reinterpret_cast<const float4*>(tau)[i];
    v.x = fminf(v.x * f, TAUCLIP);
    v.y = fminf(v.y * f, TAUCLIP);
    v.z = fminf(v.z * f, TAUCLIP);
    v.w = fminf(v.w * f, TAUCLIP);
    reinterpret_cast<float4*>(out)[i] = v;
}

__global__ void tau_fix(const float* __restrict__ tau, float* __restrict__ out) {
    int i = blockIdx.x * 256 + threadIdx.x;
    if (i >= NROW * KSEL) return;
    int row = i >> 2;
    int id = g_idx[i];
    float s = g_sig[i];
    float v = tau[(size_t)row * TT + id] * (1.0f - RHO_F) + s * s * s;
    out[(size_t)row * TT + id] = fminf(v * g_invden[row], TAUCLIP);
}

// ===================== launch ===============================================
extern "C" void kernel_launch(void* const* d_in, const int* in_sizes, int n_in,
                              void* d_out, int out_size) {
    const float* x     = (const float*)d_in[0];
    const float* tau   = (const float*)d_in[1];
    const float* Wqkv  = (const float*)d_in[2];
    const float* bqkv  = (const float*)d_in[3];
    const float* Wproj = (const float*)d_in[4];
    const float* bproj = (const float*)d_in[5];

    float* out_main = (float*)d_out;
    float* out_tau  = out_main + (size_t)NROW * CC;

    void *p_qkv, *p_ahi, *p_alo, *p_wthi, *p_wtlo, *p_wph, *p_aoh, *p_aol;
    cudaGetSymbolAddress(&p_qkv, g_qkv);
    cudaGetSymbolAddress(&p_ahi, g_a_hi);   cudaGetSymbolAddress(&p_alo, g_a_lo);
    cudaGetSymbolAddress(&p_wthi, g_wt_hi); cudaGetSymbolAddress(&p_wtlo, g_wt_lo);
    cudaGetSymbolAddress(&p_wph, g_wp_h);
    cudaGetSymbolAddress(&p_aoh, g_ao_h);   cudaGetSymbolAddress(&p_aol, g_ao_l);

    cudaFuncSetAttribute(qkv_gemm, cudaFuncAttributeMaxDynamicSharedMemorySize, QKV_SMEM);
    cudaFuncSetAttribute(proj_gemm, cudaFuncAttributeMaxDynamicSharedMemorySize, PROJ_SMEM);

    // 1-3. operand prep
    convert_split<<<(NROW * KTOT) / 256, 256>>>(x, (__nv_bfloat16*)p_ahi, (__nv_bfloat16*)p_alo, NROW * KTOT);
    transpose_split<<<dim3(C3 / 32, KTOT / 32), dim3(32, 8)>>>(Wqkv, (__nv_bfloat16*)p_wthi, (__nv_bfloat16*)p_wtlo, KTOT, C3);
    transpose_half<<<dim3(CC / 32, KTOT / 32), dim3(32, 8)>>>(Wproj, (__half*)p_wph, KTOT, CC);

    // 4. QKV GEMM (launch #4 -> gets profiled by ncu)
    qkv_gemm<<<dim3(C3 / 128, NROW / 256), 256, QKV_SMEM>>>(
        (const __nv_bfloat16*)p_ahi, (const __nv_bfloat16*)p_alo,
        (const __nv_bfloat16*)p_wthi, (const __nv_bfloat16*)p_wtlo,
        bqkv, (float*)p_qkv, C3);

    // 5. top-4 + rowsum of tau per row
    topk_kernel<<<NROW, 256>>>(tau);

    // 6. sparse attention -> fp16 hi/lo attn_out + signal + denominator
    attn_kernel<<<NROW, 256>>>(tau);

    // 7-8. tau_new
    tau_scale<<<(NROW * TT / 4) / 256, 256>>>(tau, out_tau);
    tau_fix<<<(NROW * KSEL + 255) / 256, 256>>>(tau, out_tau);

    // 9. proj GEMM (fp16 2-term) -> d_out
    proj_gemm<<<dim3(CC / 128, NROW / 128), 256, PROJ_SMEM>>>(
        (const __half*)p_aoh, (const __half*)p_aol, (const __half*)p_wph,
        bproj, out_main, CC);
}

// round 5
// speedup vs baseline: 1.3554x; 1.3554x over previous
#include <cuda_runtime.h>
#include <cuda_fp16.h>
#include <math.h>
#include <stdint.h>

// Problem constants
#define BB    2
#define TT    2048
#define CC    512
#define HH    8
#define DD    64
#define C3    1536
#define KSEL  4
#define GAMMA_F 2.5f
#define RHO_F   0.085f
#define TAUCLIP 5.0f
#define NROW  (BB*TT)       // 4096
#define KTOT  512

// ---------------- scratch (device globals) ---------------------------------
__device__ float g_qkv[(size_t)NROW * C3];        // 24 MB fp32
__device__ int   g_idx[NROW * KSEL];
__device__ float g_sig[NROW * KSEL];
__device__ float g_rowsum[NROW];
__device__ float g_invden[NROW];
// fp16 operands
__device__ __half g_x_h[(size_t)NROW * KTOT];     // x hi
__device__ __half g_x_l[(size_t)NROW * KTOT];     // x lo
__device__ __half g_wqt[(size_t)C3 * KTOT];       // Wqkv^T fp16
__device__ __half g_wpt[(size_t)CC * KTOT];       // Wproj^T fp16
__device__ __half g_ao_h[(size_t)NROW * KTOT];    // attn_out hi
__device__ __half g_ao_l[(size_t)NROW * KTOT];    // attn_out lo

// ===================== helpers ==============================================
__device__ __forceinline__ uint32_t smem_u32(const void* p) {
    uint32_t a;
    asm("{ .reg .u64 t; cvta.to.shared.u64 t, %1; cvt.u32.u64 %0, t; }" : "=r"(a) : "l"(p));
    return a;
}
__device__ __forceinline__ void ldsm_x4(uint32_t& r0, uint32_t& r1, uint32_t& r2, uint32_t& r3,
                                        uint32_t addr) {
    asm volatile("ldmatrix.sync.aligned.m8n8.x4.shared.b16 {%0,%1,%2,%3}, [%4];"
                 : "=r"(r0), "=r"(r1), "=r"(r2), "=r"(r3) : "r"(addr));
}
__device__ __forceinline__ void mma_fp16(float* d, const uint32_t* a, uint32_t b0, uint32_t b1) {
    asm volatile("mma.sync.aligned.m16n8k16.row.col.f32.f16.f16.f32 "
                 "{%0,%1,%2,%3}, {%4,%5,%6,%7}, {%8,%9}, {%0,%1,%2,%3};"
                 : "+f"(d[0]), "+f"(d[1]), "+f"(d[2]), "+f"(d[3])
                 : "r"(a[0]), "r"(a[1]), "r"(a[2]), "r"(a[3]), "r"(b0), "r"(b1));
}

// ===================== top-K + rowsum: single pass ==========================
// key = (float_bits(v) << 32) | (0x7FFFFFFF - i)  — v >= 0 so bits monotonic;
// larger key = larger value, tie -> smaller index (matches lax.top_k).
__global__ void topk_kernel(const float* __restrict__ tau) {
    const int row = blockIdx.x;
    const float* tr = tau + (size_t)row * TT;
    __shared__ unsigned long long sk[256 * 4];
    __shared__ float red[256];
    const int tid = threadIdx.x;

    unsigned long long k0 = 0, k1 = 0, k2 = 0, k3 = 0;
    float sum = 0.f;
    #pragma unroll
    for (int i = tid; i < TT; i += 256) {
        float v = tr[i];
        sum += v;
        unsigned long long key =
            ((unsigned long long)__float_as_uint(v) << 32) | (unsigned)(0x7FFFFFFF - i);
        if (key > k3) {
            if (key > k0)      { k3 = k2; k2 = k1; k1 = k0; k0 = key; }
            else if (key > k1) { k3 = k2; k2 = k1; k1 = key; }
            else if (key > k2) { k3 = k2; k2 = key; }
            else               { k3 = key; }
        }
    }
    sk[tid * 4 + 0] = k0; sk[tid * 4 + 1] = k1;
    sk[tid * 4 + 2] = k2; sk[tid * 4 + 3] = k3;
    red[tid] = sum;
    __syncthreads();

    for (int s = 128; s > 0; s >>= 1) {
        if (tid < s) {
            red[tid] += red[tid + s];
            unsigned long long a[4], b[4], o[4];
            #pragma unroll
            for (int t = 0; t < 4; t++) { a[t] = sk[tid * 4 + t]; b[t] = sk[(tid + s) * 4 + t]; }
            int ia = 0, ib = 0;
            #pragma unroll
            for (int t = 0; t < 4; t++) {
                if (a[ia] >= b[ib]) o[t] = a[ia++];
                else                o[t] = b[ib++];
            }
            #pragma unroll
            for (int t = 0; t < 4; t++) sk[tid * 4 + t] = o[t];
        }
        __syncthreads();
    }
    if (tid == 0) {
        g_rowsum[row] = red[0];
        #pragma unroll
        for (int p = 0; p < KSEL; p++) {
            unsigned long long key = sk[p];
            g_idx[row * KSEL + p] = 0x7FFFFFFF - (int)(key & 0xFFFFFFFFu);
        }
    }
}

// ===================== operand prep =========================================
__global__ void convert_split_h(const float* __restrict__ in,
                                __half* __restrict__ hi, __half* __restrict__ lo, int n) {
    int i = blockIdx.x * 256 + threadIdx.x;
    if (i < n) {
        float v = in[i];
        __half h = __float2half(v);
        hi[i] = h;
        lo[i] = __float2half(v - __half2float(h));
    }
}

// W [K,N] fp32 -> [N,K] fp16
__global__ void transpose_half(const float* __restrict__ W,
                               __half* __restrict__ out, int K, int N) {
    __shared__ float tile[32][33];
    int n0 = blockIdx.x * 32, k0 = blockIdx.y * 32;
    int tx = threadIdx.x, ty = threadIdx.y;
    #pragma unroll
    for (int i = 0; i < 32; i += 8)
        tile[ty + i][tx] = W[(size_t)(k0 + ty + i) * N + n0 + tx];
    __syncthreads();
    #pragma unroll
    for (int i = 0; i < 32; i += 8)
        out[(size_t)(n0 + ty + i) * K + k0 + tx] = __float2half(tile[tx][ty + i]);
}

// ===================== fp16 2-term GEMM (template on M-frags) ===============
// C[M,N] = (Ah+Al) * Bh^T + bias.  8 warps (4m x 2n), BN=128, BM=64*MF,
// warp tile (16*MF) x 64, K-chunk 32, 3-stage cp.async.
#define GBK 32
#define NCHUNK (KTOT / GBK)          // 16
#define RPB 80                       // bytes per padded smem row

template<int MF>
__device__ __forceinline__ void load_chunk_2t(
    uint32_t sm_base, int stage, int c, int m0, int n0, int tid,
    const __half* __restrict__ Ah, const __half* __restrict__ Al,
    const __half* __restrict__ Bh)
{
    constexpr int AT = 64 * MF * RPB;
    constexpr int BT = 128 * RPB;
    constexpr int STG = 2 * AT + BT;
    if (c < NCHUNK) {
        uint32_t sbase = sm_base + stage * STG;
        const int k0 = c * GBK;
        const __half* asrc[2] = {Ah, Al};
        #pragma unroll
        for (int t = 0; t < 2; t++) {
            #pragma unroll
            for (int i = 0; i < MF; i++) {
                int u = tid + i * 256;               // rows 64*MF x 4 c16
                int r = u >> 2, c16 = u & 3;
                const void* gp = asrc[t] + (size_t)(m0 + r) * KTOT + k0 + c16 * 8;
                uint32_t dst = sbase + t * AT + r * RPB + c16 * 16;
                asm volatile("cp.async.cg.shared.global [%0], [%1], 16;" :: "r"(dst), "l"(gp));
            }
        }
        #pragma unroll
        for (int i = 0; i < 2; i++) {                // B: 128 rows x 4 c16
            int u = tid + i * 256;
            int r = u >> 2, c16 = u & 3;
            const void* gp = Bh + (size_t)(n0 + r) * KTOT + k0 + c16 * 8;
            uint32_t dst = sbase + 2 * AT + r * RPB + c16 * 16;
            asm volatile("cp.async.cg.shared.global [%0], [%1], 16;" :: "r"(dst), "l"(gp));
        }
    }
    asm volatile("cp.async.commit_group;" ::: "memory");
}

template<int MF>
__global__ __launch_bounds__(256, 2) void gemm_fp16_2t(
    const __half* __restrict__ Ah, const __half* __restrict__ Al,
    const __half* __restrict__ Bh,
    const float* __restrict__ bias, float* __restrict__ Cout, int N)
{
    constexpr int AT = 64 * MF * RPB;
    constexpr int BT = 128 * RPB;
    constexpr int STG = 2 * AT + BT;
    extern __shared__ char smem[];
    const uint32_t sm_base = smem_u32(smem);
    const int tid = threadIdx.x;
    const int wid = tid >> 5, lane = tid & 31;
    const int wm = wid >> 1, wn = wid & 1;           // 4m x 2n
    const int m0 = blockIdx.y * (64 * MF);
    const int n0 = blockIdx.x * 128;

    float acc[MF][8][4];
    #pragma unroll
    for (int i = 0; i < MF; i++)
        #pragma unroll
        for (int j = 0; j < 8; j++)
            #pragma unroll
            for (int l = 0; l < 4; l++) acc[i][j][l] = 0.f;

    load_chunk_2t<MF>(sm_base, 0, 0, m0, n0, tid, Ah, Al, Bh);
    load_chunk_2t<MF>(sm_base, 1, 1, m0, n0, tid, Ah, Al, Bh);

    const int lrow = lane & 15;
    const int lcol = (lane >> 4) << 3;

    for (int c = 0; c < NCHUNK; c++) {
        asm volatile("cp.async.wait_group 1;" ::: "memory");
        __syncthreads();
        load_chunk_2t<MF>(sm_base, (c + 2) % 3, c + 2, m0, n0, tid, Ah, Al, Bh);

        const uint32_t stg = sm_base + (c % 3) * STG;
        #pragma unroll
        for (int kk = 0; kk < 2; kk++) {
            const int kc = kk * 16 + lcol;
            uint32_t ah[MF][4], al[MF][4];
            #pragma unroll
            for (int im = 0; im < MF; im++) {
                uint32_t ra = (wm * 16 * MF + im * 16 + lrow) * RPB + kc * 2;
                ldsm_x4(ah[im][0], ah[im][1], ah[im][2], ah[im][3], stg + ra);
                ldsm_x4(al[im][0], al[im][1], al[im][2], al[im][3], stg + AT + ra);
            }
            #pragma unroll
            for (int jn = 0; jn < 4; jn++) {
                uint32_t rb = (wn * 64 + jn * 16 + lrow) * RPB + kc * 2;
                uint32_t bh[4];
                ldsm_x4(bh[0], bh[1], bh[2], bh[3], stg + 2 * AT + rb);
                #pragma unroll
                for (int im = 0; im < MF; im++) {
                    mma_fp16(acc[im][jn * 2],     ah[im], bh[0], bh[2]);
                    mma_fp16(acc[im][jn * 2],     al[im], bh[0], bh[2]);
                    mma_fp16(acc[im][jn * 2 + 1], ah[im], bh[1], bh[3]);
                    mma_fp16(acc[im][jn * 2 + 1], al[im], bh[1], bh[3]);
                }
            }
        }
    }

    #pragma unroll
    for (int im = 0; im < MF; im++) {
        int rbase = m0 + wm * 16 * MF + im * 16 + (lane >> 2);
        #pragma unroll
        for (int jf = 0; jf < 8; jf++) {
            int col = n0 + wn * 64 + jf * 8 + (lane & 3) * 2;
            float2 b2 = *reinterpret_cast<const float2*>(bias + col);
            float2 o0, o1;
            o0.x = acc[im][jf][0] + b2.x; o0.y = acc[im][jf][1] + b2.y;
            o1.x = acc[im][jf][2] + b2.x; o1.y = acc[im][jf][3] + b2.y;
            *reinterpret_cast<float2*>(Cout + (size_t)rbase * N + col) = o0;
            *reinterpret_cast<float2*>(Cout + (size_t)(rbase + 8) * N + col) = o1;
        }
    }
}

#define QKV_SMEM (3 * (2 * (128 * RPB) + 128 * RPB))   // 92160
#define PROJ_SMEM (3 * (2 * (64 * RPB) + 128 * RPB))   // 61440

// ===================== sparse attention =====================================
__global__ __launch_bounds__(256) void attn_kernel(const float* __restrict__ tau) {
    const int row = blockIdx.x;
    const int tid = threadIdx.x;
    const int warp = tid >> 5, lane = tid & 31;   // warp == head
    const int b = row / TT;

    __shared__ int   sidx[KSEL];
    __shared__ float sbias[KSEL];
    __shared__ float ssig[KSEL];

    if (tid < KSEL) {
        int id = g_idx[row * KSEL + tid];
        sidx[tid]  = id;
        sbias[tid] = GAMMA_F * logf(tau[(size_t)row * TT + id] + 1e-8f);
        ssig[tid]  = 0.f;
    }
    __syncthreads();

    const float* qp = g_qkv + (size_t)row * C3 + warp * DD;
    const float q0 = qp[lane], q1 = qp[lane + 32];

    float logit[KSEL];
    #pragma unroll
    for (int j = 0; j < KSEL; j++) {
        int s = sidx[j];
        const float* kp = g_qkv + (size_t)(b * TT + s) * C3 + CC + warp * DD;
        float p = q0 * kp[lane] + q1 * kp[lane + 32];
        #pragma unroll
        for (int o = 16; o > 0; o >>= 1) p += __shfl_xor_sync(0xffffffffu, p, o);
        logit[j] = p * 0.125f + sbias[j];
    }
    float m = fmaxf(fmaxf(logit[0], logit[1]), fmaxf(logit[2], logit[3]));
    float e[KSEL], se = 0.f;
    #pragma unroll
    for (int j = 0; j < KSEL; j++) { e[j] = expf(logit[j] - m); se += e[j]; }
    float inv = 1.f / se;
    float w[KSEL];
    #pragma unroll
    for (int j = 0; j < KSEL; j++) w[j] = e[j] * inv;

    float o0 = 0.f, o1 = 0.f;
    #pragma unroll
    for (int j = 0; j < KSEL; j++) {
        const float* vp = g_qkv + (size_t)(b * TT + sidx[j]) * C3 + 2 * CC + warp * DD;
        o0 = fmaf(w[j], vp[lane], o0);
        o1 = fmaf(w[j], vp[lane + 32], o1);
    }
    // write attn_out as fp16 hi/lo (proj GEMM operand)
    size_t obase = (size_t)row * KTOT + warp * DD;
    __half h0 = __float2half(o0);
    __half h1 = __float2half(o1);
    g_ao_h[obase + lane]      = h0;
    g_ao_h[obase + lane + 32] = h1;
    g_ao_l[obase + lane]      = __float2half(o0 - __half2float(h0));
    g_ao_l[obase + lane + 32] = __float2half(o1 - __half2float(h1));

    if (lane == 0) {
        #pragma unroll
        for (int j = 0; j < KSEL; j++) atomicAdd(&ssig[j], w[j] * (1.0f / HH));
    }
    __syncthreads();
    if (tid == 0) {
        float rs = g_rowsum[row] * (1.0f - RHO_F);
        #pragma unroll
        for (int j = 0; j < KSEL; j++) {
            float s = ssig[j];
            g_sig[row * KSEL + j] = s;
            rs += s * s * s;
        }
        g_invden[row] = 1.f / (rs + 1e-8f);
    }
}

// ===================== tau_new passes =======================================
__global__ void tau_scale(const float* __restrict__ tau, float* __restrict__ out) {
    size_t i = (size_t)blockIdx.x * 256 + threadIdx.x;
    const int row = (int)(i / (TT / 4));
    const float f = (1.0f - RHO_F) * g_invden[row];
    float4 v = reinterpret_cast<const float4*>(tau)[i];
    v.x = fminf(v.x * f, TAUCLIP);
    v.y = fminf(v.y * f, TAUCLIP);
    v.z = fminf(v.z * f, TAUCLIP);
    v.w = fminf(v.w * f, TAUCLIP);
    reinterpret_cast<float4*>(out)[i] = v;
}

__global__ void tau_fix(const float* __restrict__ tau, float* __restrict__ out) {
    int i = blockIdx.x * 256 + threadIdx.x;
    if (i >= NROW * KSEL) return;
    int row = i >> 2;
    int id = g_idx[i];
    float s = g_sig[i];
    float v = tau[(size_t)row * TT + id] * (1.0f - RHO_F) + s * s * s;
    out[(size_t)row * TT + id] = fminf(v * g_invden[row], TAUCLIP);
}

// ===================== launch ===============================================
extern "C" void kernel_launch(void* const* d_in, const int* in_sizes, int n_in,
                              void* d_out, int out_size) {
    const float* x     = (const float*)d_in[0];
    const float* tau   = (const float*)d_in[1];
    const float* Wqkv  = (const float*)d_in[2];
    const float* bqkv  = (const float*)d_in[3];
    const float* Wproj = (const float*)d_in[4];
    const float* bproj = (const float*)d_in[5];

    float* out_main = (float*)d_out;
    float* out_tau  = out_main + (size_t)NROW * CC;

    void *p_qkv, *p_xh, *p_xl, *p_wqt, *p_wpt, *p_aoh, *p_aol;
    cudaGetSymbolAddress(&p_qkv, g_qkv);
    cudaGetSymbolAddress(&p_xh, g_x_h);   cudaGetSymbolAddress(&p_xl, g_x_l);
    cudaGetSymbolAddress(&p_wqt, g_wqt);  cudaGetSymbolAddress(&p_wpt, g_wpt);
    cudaGetSymbolAddress(&p_aoh, g_ao_h); cudaGetSymbolAddress(&p_aol, g_ao_l);

    cudaFuncSetAttribute(gemm_fp16_2t<2>, cudaFuncAttributeMaxDynamicSharedMemorySize, QKV_SMEM);
    cudaFuncSetAttribute(gemm_fp16_2t<1>, cudaFuncAttributeMaxDynamicSharedMemorySize, PROJ_SMEM);

    // 1-3. operand prep
    convert_split_h<<<(NROW * KTOT) / 256, 256>>>(x, (__half*)p_xh, (__half*)p_xl, NROW * KTOT);
    transpose_half<<<dim3(C3 / 32, KTOT / 32), dim3(32, 8)>>>(Wqkv, (__half*)p_wqt, KTOT, C3);
    transpose_half<<<dim3(CC / 32, KTOT / 32), dim3(32, 8)>>>(Wproj, (__half*)p_wpt, KTOT, CC);

    // 4. QKV GEMM (fp16 2-term), 384 CTAs, 2 CTAs/SM
    gemm_fp16_2t<2><<<dim3(C3 / 128, NROW / 128), 256, QKV_SMEM>>>(
        (const __half*)p_xh, (const __half*)p_xl, (const __half*)p_wqt,
        bqkv, (float*)p_qkv, C3);

    // 5. top-4 + rowsum of tau per row (single pass)
    topk_kernel<<<NROW, 256>>>(tau);

    // 6. sparse attention -> fp16 hi/lo attn_out + signal + denominator
    attn_kernel<<<NROW, 256>>>(tau);

    // 7-8. tau_new
    tau_scale<<<(NROW * TT / 4) / 256, 256>>>(tau, out_tau);
    tau_fix<<<(NROW * KSEL + 255) / 256, 256>>>(tau, out_tau);

    // 9. proj GEMM (fp16 2-term), 256 CTAs
    gemm_fp16_2t<1><<<dim3(CC / 128, NROW / 64), 256, PROJ_SMEM>>>(
        (const __half*)p_aoh, (const __half*)p_aol, (const __half*)p_wpt,
        bproj, out_main, CC);
}

// round 6
// speedup vs baseline: 1.4414x; 1.0635x over previous
#include <cuda_runtime.h>
#include <cuda_fp16.h>
#include <math.h>
#include <stdint.h>

// Problem constants
#define BB    2
#define TT    2048
#define CC    512
#define HH    8
#define DD    64
#define C3    1536
#define KSEL  4
#define GAMMA_F 2.5f
#define RHO_F   0.085f
#define TAUCLIP 5.0f
#define NROW  (BB*TT)       // 4096
#define KTOT  512

// ---------------- scratch (device globals) ---------------------------------
__device__ float g_qkv[(size_t)NROW * C3];        // 24 MB fp32
__device__ int   g_idx[NROW * KSEL];
__device__ float g_rowsum[NROW];
// fp16 operands
__device__ __half g_x_h[(size_t)NROW * KTOT];     // x hi
__device__ __half g_x_l[(size_t)NROW * KTOT];     // x lo
__device__ __half g_wqt[(size_t)C3 * KTOT];       // Wqkv^T fp16
__device__ __half g_wpt[(size_t)CC * KTOT];       // Wproj^T fp16
__device__ __half g_ao_h[(size_t)NROW * KTOT];    // attn_out hi
__device__ __half g_ao_l[(size_t)NROW * KTOT];    // attn_out lo

// ===================== helpers ==============================================
__device__ __forceinline__ uint32_t smem_u32(const void* p) {
    uint32_t a;
    asm("{ .reg .u64 t; cvta.to.shared.u64 t, %1; cvt.u32.u64 %0, t; }" : "=r"(a) : "l"(p));
    return a;
}
__device__ __forceinline__ void ldsm_x4(uint32_t& r0, uint32_t& r1, uint32_t& r2, uint32_t& r3,
                                        uint32_t addr) {
    asm volatile("ldmatrix.sync.aligned.m8n8.x4.shared.b16 {%0,%1,%2,%3}, [%4];"
                 : "=r"(r0), "=r"(r1), "=r"(r2), "=r"(r3) : "r"(addr));
}
__device__ __forceinline__ void mma_fp16(float* d, const uint32_t* a, uint32_t b0, uint32_t b1) {
    asm volatile("mma.sync.aligned.m16n8k16.row.col.f32.f16.f16.f32 "
                 "{%0,%1,%2,%3}, {%4,%5,%6,%7}, {%8,%9}, {%0,%1,%2,%3};"
                 : "+f"(d[0]), "+f"(d[1]), "+f"(d[2]), "+f"(d[3])
                 : "r"(a[0]), "r"(a[1]), "r"(a[2]), "r"(a[3]), "r"(b0), "r"(b1));
}

// ===================== top-K + rowsum: single pass ==========================
// key = (float_bits(v) << 32) | (0x7FFFFFFF - i); v >= 0 so bits monotonic;
// larger key = larger value, tie -> smaller index (matches lax.top_k).
__global__ void topk_kernel(const float* __restrict__ tau) {
    const int row = blockIdx.x;
    const float* tr = tau + (size_t)row * TT;
    __shared__ unsigned long long sk[256 * 4];
    __shared__ float red[256];
    const int tid = threadIdx.x;

    unsigned long long k0 = 0, k1 = 0, k2 = 0, k3 = 0;
    float sum = 0.f;
    #pragma unroll
    for (int i = tid; i < TT; i += 256) {
        float v = tr[i];
        sum += v;
        unsigned long long key =
            ((unsigned long long)__float_as_uint(v) << 32) | (unsigned)(0x7FFFFFFF - i);
        if (key > k3) {
            if (key > k0)      { k3 = k2; k2 = k1; k1 = k0; k0 = key; }
            else if (key > k1) { k3 = k2; k2 = k1; k1 = key; }
            else if (key > k2) { k3 = k2; k2 = key; }
            else               { k3 = key; }
        }
    }
    sk[tid * 4 + 0] = k0; sk[tid * 4 + 1] = k1;
    sk[tid * 4 + 2] = k2; sk[tid * 4 + 3] = k3;
    red[tid] = sum;
    __syncthreads();

    for (int s = 128; s > 0; s >>= 1) {
        if (tid < s) {
            red[tid] += red[tid + s];
            unsigned long long a[4], b[4], o[4];
            #pragma unroll
            for (int t = 0; t < 4; t++) { a[t] = sk[tid * 4 + t]; b[t] = sk[(tid + s) * 4 + t]; }
            int ia = 0, ib = 0;
            #pragma unroll
            for (int t = 0; t < 4; t++) {
                if (a[ia] >= b[ib]) o[t] = a[ia++];
                else                o[t] = b[ib++];
            }
            #pragma unroll
            for (int t = 0; t < 4; t++) sk[tid * 4 + t] = o[t];
        }
        __syncthreads();
    }
    if (tid == 0) {
        g_rowsum[row] = red[0];
        #pragma unroll
        for (int p = 0; p < KSEL; p++) {
            unsigned long long key = sk[p];
            g_idx[row * KSEL + p] = 0x7FFFFFFF - (int)(key & 0xFFFFFFFFu);
        }
    }
}

// ===================== operand prep =========================================
__global__ void convert_split_h(const float* __restrict__ in,
                                __half* __restrict__ hi, __half* __restrict__ lo, int n) {
    int i = blockIdx.x * 256 + threadIdx.x;
    if (i < n) {
        float v = in[i];
        __half h = __float2half(v);
        hi[i] = h;
        lo[i] = __float2half(v - __half2float(h));
    }
}

// W [K,N] fp32 -> [N,K] fp16
__global__ void transpose_half(const float* __restrict__ W,
                               __half* __restrict__ out, int K, int N) {
    __shared__ float tile[32][33];
    int n0 = blockIdx.x * 32, k0 = blockIdx.y * 32;
    int tx = threadIdx.x, ty = threadIdx.y;
    #pragma unroll
    for (int i = 0; i < 32; i += 8)
        tile[ty + i][tx] = W[(size_t)(k0 + ty + i) * N + n0 + tx];
    __syncthreads();
    #pragma unroll
    for (int i = 0; i < 32; i += 8)
        out[(size_t)(n0 + ty + i) * K + k0 + tx] = __float2half(tile[tx][ty + i]);
}

// ===================== fp16 GEMM: hi-term always, lo-term if n0>=lo_start ===
// C[M,N] = (Ah [+ Al]) * Bh^T + bias.  8 warps (4m x 2n), BN=128, BM=64*MF,
// warp tile (16*MF) x 64, K-chunk 32, 3-stage cp.async.
#define GBK 32
#define NCHUNK (KTOT / GBK)          // 16
#define RPB 80                       // bytes per padded smem row

template<int MF>
__device__ __forceinline__ void load_chunk_2t(
    uint32_t sm_base, int stage, int c, int m0, int n0, int tid, bool use_lo,
    const __half* __restrict__ Ah, const __half* __restrict__ Al,
    const __half* __restrict__ Bh)
{
    constexpr int AT = 64 * MF * RPB;
    constexpr int BT = 128 * RPB;
    constexpr int STG = 2 * AT + BT;
    if (c < NCHUNK) {
        uint32_t sbase = sm_base + stage * STG;
        const int k0 = c * GBK;
        #pragma unroll
        for (int i = 0; i < MF; i++) {
            int u = tid + i * 256;
            int r = u >> 2, c16 = u & 3;
            const void* gp = Ah + (size_t)(m0 + r) * KTOT + k0 + c16 * 8;
            uint32_t dst = sbase + r * RPB + c16 * 16;
            asm volatile("cp.async.cg.shared.global [%0], [%1], 16;" :: "r"(dst), "l"(gp));
        }
        if (use_lo) {
            #pragma unroll
            for (int i = 0; i < MF; i++) {
                int u = tid + i * 256;
                int r = u >> 2, c16 = u & 3;
                const void* gp = Al + (size_t)(m0 + r) * KTOT + k0 + c16 * 8;
                uint32_t dst = sbase + AT + r * RPB + c16 * 16;
                asm volatile("cp.async.cg.shared.global [%0], [%1], 16;" :: "r"(dst), "l"(gp));
            }
        }
        #pragma unroll
        for (int i = 0; i < 2; i++) {
            int u = tid + i * 256;
            int r = u >> 2, c16 = u & 3;
            const void* gp = Bh + (size_t)(n0 + r) * KTOT + k0 + c16 * 8;
            uint32_t dst = sbase + 2 * AT + r * RPB + c16 * 16;
            asm volatile("cp.async.cg.shared.global [%0], [%1], 16;" :: "r"(dst), "l"(gp));
        }
    }
    asm volatile("cp.async.commit_group;" ::: "memory");
}

template<int MF>
__global__ __launch_bounds__(256, 2) void gemm_fp16_2t(
    const __half* __restrict__ Ah, const __half* __restrict__ Al,
    const __half* __restrict__ Bh,
    const float* __restrict__ bias, float* __restrict__ Cout,
    int N, int nt_shift, int nt_mod, int lo_start)
{
    constexpr int AT = 64 * MF * RPB;
    constexpr int BT = 128 * RPB;
    constexpr int STG = 2 * AT + BT;
    extern __shared__ char smem[];
    const uint32_t sm_base = smem_u32(smem);
    const int tid = threadIdx.x;
    const int wid = tid >> 5, lane = tid & 31;
    const int wm = wid >> 1, wn = wid & 1;
    const int m0 = blockIdx.y * (64 * MF);
    const int n0 = ((blockIdx.x + nt_shift) % nt_mod) * 128;
    const bool use_lo = (n0 >= lo_start);

    float acc[MF][8][4];
    #pragma unroll
    for (int i = 0; i < MF; i++)
        #pragma unroll
        for (int j = 0; j < 8; j++)
            #pragma unroll
            for (int l = 0; l < 4; l++) acc[i][j][l] = 0.f;

    load_chunk_2t<MF>(sm_base, 0, 0, m0, n0, tid, use_lo, Ah, Al, Bh);
    load_chunk_2t<MF>(sm_base, 1, 1, m0, n0, tid, use_lo, Ah, Al, Bh);

    const int lrow = lane & 15;
    const int lcol = (lane >> 4) << 3;

    for (int c = 0; c < NCHUNK; c++) {
        asm volatile("cp.async.wait_group 1;" ::: "memory");
        __syncthreads();
        load_chunk_2t<MF>(sm_base, (c + 2) % 3, c + 2, m0, n0, tid, use_lo, Ah, Al, Bh);

        const uint32_t stg = sm_base + (c % 3) * STG;
        #pragma unroll
        for (int kk = 0; kk < 2; kk++) {
            const int kc = kk * 16 + lcol;
            uint32_t ah[MF][4], al[MF][4];
            #pragma unroll
            for (int im = 0; im < MF; im++) {
                uint32_t ra = (wm * 16 * MF + im * 16 + lrow) * RPB + kc * 2;
                ldsm_x4(ah[im][0], ah[im][1], ah[im][2], ah[im][3], stg + ra);
                if (use_lo)
                    ldsm_x4(al[im][0], al[im][1], al[im][2], al[im][3], stg + AT + ra);
            }
            #pragma unroll
            for (int jn = 0; jn < 4; jn++) {
                uint32_t rb = (wn * 64 + jn * 16 + lrow) * RPB + kc * 2;
                uint32_t bh[4];
                ldsm_x4(bh[0], bh[1], bh[2], bh[3], stg + 2 * AT + rb);
                #pragma unroll
                for (int im = 0; im < MF; im++) {
                    mma_fp16(acc[im][jn * 2],     ah[im], bh[0], bh[2]);
                    mma_fp16(acc[im][jn * 2 + 1], ah[im], bh[1], bh[3]);
                    if (use_lo) {
                        mma_fp16(acc[im][jn * 2],     al[im], bh[0], bh[2]);
                        mma_fp16(acc[im][jn * 2 + 1], al[im], bh[1], bh[3]);
                    }
                }
            }
        }
    }

    #pragma unroll
    for (int im = 0; im < MF; im++) {
        int rbase = m0 + wm * 16 * MF + im * 16 + (lane >> 2);
        #pragma unroll
        for (int jf = 0; jf < 8; jf++) {
            int col = n0 + wn * 64 + jf * 8 + (lane & 3) * 2;
            float2 b2 = *reinterpret_cast<const float2*>(bias + col);
            float2 o0, o1;
            o0.x = acc[im][jf][0] + b2.x; o0.y = acc[im][jf][1] + b2.y;
            o1.x = acc[im][jf][2] + b2.x; o1.y = acc[im][jf][3] + b2.y;
            *reinterpret_cast<float2*>(Cout + (size_t)rbase * N + col) = o0;
            *reinterpret_cast<float2*>(Cout + (size_t)(rbase + 8) * N + col) = o1;
        }
    }
}

#define QKV_SMEM (3 * (2 * (128 * RPB) + 128 * RPB))   // 92160
#define PROJ_SMEM (3 * (2 * (64 * RPB) + 128 * RPB))   // 61440

// ===================== fused attention + tau_new ============================
// One block per (b,t) row: sparse attention (warp=head), EMA signal, then
// stream-scale the tau row and patch the 4 selected entries.
__global__ __launch_bounds__(256) void attn_fused(const float* __restrict__ tau,
                                                  float* __restrict__ out_tau) {
    const int row = blockIdx.x;
    const int tid = threadIdx.x;
    const int warp = tid >> 5, lane = tid & 31;   // warp == head
    const int b = row / TT;

    __shared__ int   sidx[KSEL];
    __shared__ float sbias[KSEL];
    __shared__ float stval[KSEL];
    __shared__ float ssig[KSEL];
    __shared__ float sinv;

    if (tid < KSEL) {
        int id = g_idx[row * KSEL + tid];
        float tv = tau[(size_t)row * TT + id];
        sidx[tid]  = id;
        stval[tid] = tv;
        sbias[tid] = GAMMA_F * logf(tv + 1e-8f);
        ssig[tid]  = 0.f;
    }
    __syncthreads();

    const float* qp = g_qkv + (size_t)row * C3 + warp * DD;
    const float q0 = qp[lane], q1 = qp[lane + 32];

    float logit[KSEL];
    #pragma unroll
    for (int j = 0; j < KSEL; j++) {
        int s = sidx[j];
        const float* kp = g_qkv + (size_t)(b * TT + s) * C3 + CC + warp * DD;
        float p = q0 * kp[lane] + q1 * kp[lane + 32];
        #pragma unroll
        for (int o = 16; o > 0; o >>= 1) p += __shfl_xor_sync(0xffffffffu, p, o);
        logit[j] = p * 0.125f + sbias[j];
    }
    float m = fmaxf(fmaxf(logit[0], logit[1]), fmaxf(logit[2], logit[3]));
    float e[KSEL], se = 0.f;
    #pragma unroll
    for (int j = 0; j < KSEL; j++) { e[j] = expf(logit[j] - m); se += e[j]; }
    float inv = 1.f / se;
    float w[KSEL];
    #pragma unroll
    for (int j = 0; j < KSEL; j++) w[j] = e[j] * inv;

    float o0 = 0.f, o1 = 0.f;
    #pragma unroll
    for (int j = 0; j < KSEL; j++) {
        const float* vp = g_qkv + (size_t)(b * TT + sidx[j]) * C3 + 2 * CC + warp * DD;
        o0 = fmaf(w[j], vp[lane], o0);
        o1 = fmaf(w[j], vp[lane + 32], o1);
    }
    // attn_out as fp16 hi/lo (proj GEMM operand)
    size_t obase = (size_t)row * KTOT + warp * DD;
    __half h0 = __float2half(o0);
    __half h1 = __float2half(o1);
    g_ao_h[obase + lane]      = h0;
    g_ao_h[obase + lane + 32] = h1;
    g_ao_l[obase + lane]      = __float2half(o0 - __half2float(h0));
    g_ao_l[obase + lane + 32] = __float2half(o1 - __half2float(h1));

    if (lane == 0) {
        #pragma unroll
        for (int j = 0; j < KSEL; j++) atomicAdd(&ssig[j], w[j] * (1.0f / HH));
    }
    __syncthreads();
    if (tid == 0) {
        float rs = g_rowsum[row] * (1.0f - RHO_F);
        #pragma unroll
        for (int j = 0; j < KSEL; j++) { float s = ssig[j]; rs += s * s * s; }
        sinv = 1.f / (rs + 1e-8f);
    }
    __syncthreads();

    // stream-scale the tau row: 512 float4s, 2 per thread
    const float f = (1.0f - RHO_F) * sinv;
    const float4* tin = reinterpret_cast<const float4*>(tau + (size_t)row * TT);
    float4* tout = reinterpret_cast<float4*>(out_tau + (size_t)row * TT);
    #pragma unroll
    for (int t = 0; t < 2; t++) {
        int i = tid + t * 256;
        float4 v = tin[i];
        v.x = fminf(v.x * f, TAUCLIP);
        v.y = fminf(v.y * f, TAUCLIP);
        v.z = fminf(v.z * f, TAUCLIP);
        v.w = fminf(v.w * f, TAUCLIP);
        tout[i] = v;
    }
    __syncthreads();
    // patch the 4 selected entries
    if (tid < KSEL) {
        float s = ssig[tid];
        float v = stval[tid] * (1.0f - RHO_F) + s * s * s;
        out_tau[(size_t)row * TT + sidx[tid]] = fminf(v * sinv, TAUCLIP);
    }
}

// ===================== launch ===============================================
extern "C" void kernel_launch(void* const* d_in, const int* in_sizes, int n_in,
                              void* d_out, int out_size) {
    const float* x     = (const float*)d_in[0];
    const float* tau   = (const float*)d_in[1];
    const float* Wqkv  = (const float*)d_in[2];
    const float* bqkv  = (const float*)d_in[3];
    const float* Wproj = (const float*)d_in[4];
    const float* bproj = (const float*)d_in[5];

    float* out_main = (float*)d_out;
    float* out_tau  = out_main + (size_t)NROW * CC;

    void *p_qkv, *p_xh, *p_xl, *p_wqt, *p_wpt, *p_aoh, *p_aol;
    cudaGetSymbolAddress(&p_qkv, g_qkv);
    cudaGetSymbolAddress(&p_xh, g_x_h);   cudaGetSymbolAddress(&p_xl, g_x_l);
    cudaGetSymbolAddress(&p_wqt, g_wqt);  cudaGetSymbolAddress(&p_wpt, g_wpt);
    cudaGetSymbolAddress(&p_aoh, g_ao_h); cudaGetSymbolAddress(&p_aol, g_ao_l);

    cudaFuncSetAttribute(gemm_fp16_2t<2>, cudaFuncAttributeMaxDynamicSharedMemorySize, QKV_SMEM);
    cudaFuncSetAttribute(gemm_fp16_2t<1>, cudaFuncAttributeMaxDynamicSharedMemorySize, PROJ_SMEM);

    // 1-3. operand prep
    convert_split_h<<<(NROW * KTOT) / 256, 256>>>(x, (__half*)p_xh, (__half*)p_xl, NROW * KTOT);
    transpose_half<<<dim3(C3 / 32, KTOT / 32), dim3(32, 8)>>>(Wqkv, (__half*)p_wqt, KTOT, C3);
    transpose_half<<<dim3(CC / 32, KTOT / 32), dim3(32, 8)>>>(Wproj, (__half*)p_wpt, KTOT, CC);

    // 4. QKV GEMM: hi for all N, lo only for V cols (n0 >= 1024).
    //    n-tile remap (+8 mod 12) puts the heavier V tiles in wave 1.
    gemm_fp16_2t<2><<<dim3(C3 / 128, NROW / 128), 256, QKV_SMEM>>>(
        (const __half*)p_xh, (const __half*)p_xl, (const __half*)p_wqt,
        bqkv, (float*)p_qkv, C3, 8, 12, 1024);

    // 5. top-4 + rowsum of tau per row (single pass)
    topk_kernel<<<NROW, 256>>>(tau);

    // 6. fused: sparse attention + signal + tau_new (scale + patch)
    attn_fused<<<NROW, 256>>>(tau, out_tau);

    // 7. proj GEMM (fp16 2-term) -> d_out
    gemm_fp16_2t<1><<<dim3(CC / 128, NROW / 64), 256, PROJ_SMEM>>>(
        (const __half*)p_aoh, (const __half*)p_aol, (const __half*)p_wpt,
        bproj, out_main, CC, 0, 4, 0);
}

// round 7
// speedup vs baseline: 1.8225x; 1.2644x over previous
#include <cuda_runtime.h>
#include <cuda_fp16.h>
#include <math.h>
#include <stdint.h>

// Problem constants
#define BB    2
#define TT    2048
#define CC    512
#define HH    8
#define DD    64
#define C3    1536
#define KSEL  4
#define GAMMA_F 2.5f
#define RHO_F   0.085f
#define TAUCLIP 5.0f
#define NROW  (BB*TT)       // 4096
#define KTOT  512

// ---------------- scratch (device globals) ---------------------------------
__device__ float g_qkv[(size_t)NROW * C3];        // 24 MB fp32
// fp16 operands
__device__ __half g_x_h[(size_t)NROW * KTOT];     // x hi
__device__ __half g_x_l[(size_t)NROW * KTOT];     // x lo
__device__ __half g_wqt[(size_t)C3 * KTOT];       // Wqkv^T fp16
__device__ __half g_wpt[(size_t)CC * KTOT];       // Wproj^T fp16
__device__ __half g_ao_h[(size_t)NROW * KTOT];    // attn_out hi
__device__ __half g_ao_l[(size_t)NROW * KTOT];    // attn_out lo

// ===================== helpers ==============================================
__device__ __forceinline__ uint32_t smem_u32(const void* p) {
    uint32_t a;
    asm("{ .reg .u64 t; cvta.to.shared.u64 t, %1; cvt.u32.u64 %0, t; }" : "=r"(a) : "l"(p));
    return a;
}
__device__ __forceinline__ void ldsm_x4(uint32_t& r0, uint32_t& r1, uint32_t& r2, uint32_t& r3,
                                        uint32_t addr) {
    asm volatile("ldmatrix.sync.aligned.m8n8.x4.shared.b16 {%0,%1,%2,%3}, [%4];"
                 : "=r"(r0), "=r"(r1), "=r"(r2), "=r"(r3) : "r"(addr));
}
__device__ __forceinline__ void mma_fp16(float* d, const uint32_t* a, uint32_t b0, uint32_t b1) {
    asm volatile("mma.sync.aligned.m16n8k16.row.col.f32.f16.f16.f32 "
                 "{%0,%1,%2,%3}, {%4,%5,%6,%7}, {%8,%9}, {%0,%1,%2,%3};"
                 : "+f"(d[0]), "+f"(d[1]), "+f"(d[2]), "+f"(d[3])
                 : "r"(a[0]), "r"(a[1]), "r"(a[2]), "r"(a[3]), "r"(b0), "r"(b1));
}

// ===================== operand prep (vectorized) ============================
__global__ void convert_split_h(const float* __restrict__ in,
                                __half* __restrict__ hi, __half* __restrict__ lo, int n4) {
    int i = blockIdx.x * 256 + threadIdx.x;     // float4 index
    if (i < n4) {
        float4 v = reinterpret_cast<const float4*>(in)[i];
        __half2 h01 = __floats2half2_rn(v.x, v.y);
        __half2 h23 = __floats2half2_rn(v.z, v.w);
        __half2 l01 = __floats2half2_rn(v.x - __half2float(__low2half(h01)),
                                        v.y - __half2float(__high2half(h01)));
        __half2 l23 = __floats2half2_rn(v.z - __half2float(__low2half(h23)),
                                        v.w - __half2float(__high2half(h23)));
        reinterpret_cast<__half2*>(hi)[i * 2]     = h01;
        reinterpret_cast<__half2*>(hi)[i * 2 + 1] = h23;
        reinterpret_cast<__half2*>(lo)[i * 2]     = l01;
        reinterpret_cast<__half2*>(lo)[i * 2 + 1] = l23;
    }
}

// W [K,N] fp32 -> [N,K] fp16
__global__ void transpose_half(const float* __restrict__ W,
                               __half* __restrict__ out, int K, int N) {
    __shared__ float tile[32][33];
    int n0 = blockIdx.x * 32, k0 = blockIdx.y * 32;
    int tx = threadIdx.x, ty = threadIdx.y;
    #pragma unroll
    for (int i = 0; i < 32; i += 8)
        tile[ty + i][tx] = W[(size_t)(k0 + ty + i) * N + n0 + tx];
    __syncthreads();
    #pragma unroll
    for (int i = 0; i < 32; i += 8)
        out[(size_t)(n0 + ty + i) * K + k0 + tx] = __float2half(tile[tx][ty + i]);
}

// ===================== QKV GEMM: K-chunk 64, 2-stage, swizzled ==============
// C[4096,1536] = (Xh [+ Xl for V cols]) * Wq^T + bias.
// BM=128, BN=128, 8 warps (4m x 2n), warp 32x64.  Tiles: 128 rows x 128B,
// XOR swizzle: unit' = unit ^ (row & 7).
#define Q64_TILE 16384
#define Q64_STAGE (3 * Q64_TILE)     // Ah, Al, Bh
#define Q64_SMEM (2 * Q64_STAGE)     // 98304
#define Q64_NCH 8                    // 512 / 64

__device__ __forceinline__ void q64_load(
    uint32_t sm_base, int stage, int c, int m0, int n0, int tid, bool use_lo,
    const __half* __restrict__ Ah, const __half* __restrict__ Al,
    const __half* __restrict__ Bh)
{
    if (c < Q64_NCH) {
        uint32_t sbase = sm_base + stage * Q64_STAGE;
        const int k0 = c * 64;
        #pragma unroll
        for (int i = 0; i < 4; i++) {
            int u = tid + i * 256;           // 0..1023
            int r = u >> 3, cu = u & 7;
            const void* gp = Ah + (size_t)(m0 + r) * KTOT + k0 + cu * 8;
            uint32_t dst = sbase + r * 128 + ((cu ^ (r & 7)) << 4);
            asm volatile("cp.async.cg.shared.global [%0], [%1], 16;" :: "r"(dst), "l"(gp));
        }
        if (use_lo) {
            #pragma unroll
            for (int i = 0; i < 4; i++) {
                int u = tid + i * 256;
                int r = u >> 3, cu = u & 7;
                const void* gp = Al + (size_t)(m0 + r) * KTOT + k0 + cu * 8;
                uint32_t dst = sbase + Q64_TILE + r * 128 + ((cu ^ (r & 7)) << 4);
                asm volatile("cp.async.cg.shared.global [%0], [%1], 16;" :: "r"(dst), "l"(gp));
            }
        }
        #pragma unroll
        for (int i = 0; i < 4; i++) {
            int u = tid + i * 256;
            int r = u >> 3, cu = u & 7;
            const void* gp = Bh + (size_t)(n0 + r) * KTOT + k0 + cu * 8;
            uint32_t dst = sbase + 2 * Q64_TILE + r * 128 + ((cu ^ (r & 7)) << 4);
            asm volatile("cp.async.cg.shared.global [%0], [%1], 16;" :: "r"(dst), "l"(gp));
        }
    }
    asm volatile("cp.async.commit_group;" ::: "memory");
}

__global__ __launch_bounds__(256, 2) void qkv_gemm64(
    const __half* __restrict__ Ah, const __half* __restrict__ Al,
    const __half* __restrict__ Bh,
    const float* __restrict__ bias, float* __restrict__ Cout)
{
    extern __shared__ char smem[];
    const uint32_t sm_base = smem_u32(smem);
    const int tid = threadIdx.x;
    const int wid = tid >> 5, lane = tid & 31;
    const int wm = wid >> 1, wn = wid & 1;
    const int m0 = blockIdx.y * 128;
    const int n0 = ((blockIdx.x + 8) % 12) * 128;     // heavy V tiles first
    const bool use_lo = (n0 >= 2 * CC);               // V columns only

    float acc[2][8][4];
    #pragma unroll
    for (int i = 0; i < 2; i++)
        #pragma unroll
        for (int j = 0; j < 8; j++)
            #pragma unroll
            for (int l = 0; l < 4; l++) acc[i][j][l] = 0.f;

    q64_load(sm_base, 0, 0, m0, n0, tid, use_lo, Ah, Al, Bh);
    q64_load(sm_base, 1, 1, m0, n0, tid, use_lo, Ah, Al, Bh);

    const int lrow = lane & 15;                       // row within 16-row group
    const int lu8 = (lane >> 4);                      // k16-half: unit offset 0/1

    for (int c = 0; c < Q64_NCH; c++) {
        asm volatile("cp.async.wait_group 1;" ::: "memory");
        __syncthreads();
        const uint32_t stg = sm_base + (c & 1) * Q64_STAGE;

        #pragma unroll
        for (int kk = 0; kk < 4; kk++) {              // four k16 steps
            const int ubase = kk * 2 + lu8;           // 16B-unit column index
            uint32_t ah[2][4], al[2][4];
            #pragma unroll
            for (int im = 0; im < 2; im++) {
                int r = wm * 32 + im * 16 + lrow;
                uint32_t ra = stg + r * 128 + ((ubase ^ (r & 7)) << 4);
                ldsm_x4(ah[im][0], ah[im][1], ah[im][2], ah[im][3], ra);
                if (use_lo)
                    ldsm_x4(al[im][0], al[im][1], al[im][2], al[im][3], ra + Q64_TILE);
            }
            #pragma unroll
            for (int jn = 0; jn < 4; jn++) {
                int r = wn * 64 + jn * 16 + lrow;
                uint32_t rb = stg + 2 * Q64_TILE + r * 128 + ((ubase ^ (r & 7)) << 4);
                uint32_t bh[4];
                ldsm_x4(bh[0], bh[1], bh[2], bh[3], rb);
                #pragma unroll
                for (int im = 0; im < 2; im++) {
                    mma_fp16(acc[im][jn * 2],     ah[im], bh[0], bh[2]);
                    mma_fp16(acc[im][jn * 2 + 1], ah[im], bh[1], bh[3]);
                    if (use_lo) {
                        mma_fp16(acc[im][jn * 2],     al[im], bh[0], bh[2]);
                        mma_fp16(acc[im][jn * 2 + 1], al[im], bh[1], bh[3]);
                    }
                }
            }
        }
        __syncthreads();
        q64_load(sm_base, c & 1, c + 2, m0, n0, tid, use_lo, Ah, Al, Bh);
    }

    #pragma unroll
    for (int im = 0; im < 2; im++) {
        int rbase = m0 + wm * 32 + im * 16 + (lane >> 2);
        #pragma unroll
        for (int jf = 0; jf < 8; jf++) {
            int col = n0 + wn * 64 + jf * 8 + (lane & 3) * 2;
            float2 b2 = *reinterpret_cast<const float2*>(bias + col);
            float2 o0, o1;
            o0.x = acc[im][jf][0] + b2.x; o0.y = acc[im][jf][1] + b2.y;
            o1.x = acc[im][jf][2] + b2.x; o1.y = acc[im][jf][3] + b2.y;
            *reinterpret_cast<float2*>(Cout + (size_t)rbase * C3 + col) = o0;
            *reinterpret_cast<float2*>(Cout + (size_t)(rbase + 8) * C3 + col) = o1;
        }
    }
}

// ===================== proj GEMM: fp16 2-term, 64x128, 3-stage ==============
#define GBK 32
#define NCHUNK (KTOT / GBK)          // 16
#define RPB 80
#define P_AT (64 * RPB)
#define P_BT (128 * RPB)
#define P_STG (2 * P_AT + P_BT)
#define PROJ_SMEM (3 * P_STG)        // 61440

__device__ __forceinline__ void proj_load(
    uint32_t sm_base, int stage, int c, int m0, int n0, int tid,
    const __half* __restrict__ Ah, const __half* __restrict__ Al,
    const __half* __restrict__ Bh)
{
    if (c < NCHUNK) {
        uint32_t sbase = sm_base + stage * P_STG;
        const int k0 = c * GBK;
        {
            int u = tid;                      // 64 rows x 4 units = 256
            int r = u >> 2, c16 = u & 3;
            const void* gp = Ah + (size_t)(m0 + r) * KTOT + k0 + c16 * 8;
            uint32_t dst = sbase + r * RPB + c16 * 16;
            asm volatile("cp.async.cg.shared.global [%0], [%1], 16;" :: "r"(dst), "l"(gp));
            gp = Al + (size_t)(m0 + r) * KTOT + k0 + c16 * 8;
            dst = sbase + P_AT + r * RPB + c16 * 16;
            asm volatile("cp.async.cg.shared.global [%0], [%1], 16;" :: "r"(dst), "l"(gp));
        }
        #pragma unroll
        for (int i = 0; i < 2; i++) {
            int u = tid + i * 256;
            int r = u >> 2, c16 = u & 3;
            const void* gp = Bh + (size_t)(n0 + r) * KTOT + k0 + c16 * 8;
            uint32_t dst = sbase + 2 * P_AT + r * RPB + c16 * 16;
            asm volatile("cp.async.cg.shared.global [%0], [%1], 16;" :: "r"(dst), "l"(gp));
        }
    }
    asm volatile("cp.async.commit_group;" ::: "memory");
}

__global__ __launch_bounds__(256, 2) void proj_gemm(
    const __half* __restrict__ Ah, const __half* __restrict__ Al,
    const __half* __restrict__ Bh,
    const float* __restrict__ bias, float* __restrict__ Cout)
{
    extern __shared__ char smem[];
    const uint32_t sm_base = smem_u32(smem);
    const int tid = threadIdx.x;
    const int wid = tid >> 5, lane = tid & 31;
    const int wm = wid >> 1, wn = wid & 1;
    const int m0 = blockIdx.y * 64;
    const int n0 = blockIdx.x * 128;

    float acc[8][4];
    #pragma unroll
    for (int j = 0; j < 8; j++)
        #pragma unroll
        for (int l = 0; l < 4; l++) acc[j][l] = 0.f;

    proj_load(sm_base, 0, 0, m0, n0, tid, Ah, Al, Bh);
    proj_load(sm_base, 1, 1, m0, n0, tid, Ah, Al, Bh);

    const int lrow = lane & 15;
    const int lcol = (lane >> 4) << 3;

    for (int c = 0; c < NCHUNK; c++) {
        asm volatile("cp.async.wait_group 1;" ::: "memory");
        __syncthreads();
        proj_load(sm_base, (c + 2) % 3, c + 2, m0, n0, tid, Ah, Al, Bh);

        const uint32_t stg = sm_base + (c % 3) * P_STG;
        #pragma unroll
        for (int kk = 0; kk < 2; kk++) {
            const int kc = kk * 16 + lcol;
            uint32_t a_h[4], a_l[4];
            uint32_t ra = (wm * 16 + lrow) * RPB + kc * 2;
            ldsm_x4(a_h[0], a_h[1], a_h[2], a_h[3], stg + ra);
            ldsm_x4(a_l[0], a_l[1], a_l[2], a_l[3], stg + P_AT + ra);
            #pragma unroll
            for (int jn = 0; jn < 4; jn++) {
                uint32_t rb = (wn * 64 + jn * 16 + lrow) * RPB + kc * 2;
                uint32_t bh[4];
                ldsm_x4(bh[0], bh[1], bh[2], bh[3], stg + 2 * P_AT + rb);
                mma_fp16(acc[jn * 2],     a_h, bh[0], bh[2]);
                mma_fp16(acc[jn * 2],     a_l, bh[0], bh[2]);
                mma_fp16(acc[jn * 2 + 1], a_h, bh[1], bh[3]);
                mma_fp16(acc[jn * 2 + 1], a_l, bh[1], bh[3]);
            }
        }
    }

    {
        int rbase = m0 + wm * 16 + (lane >> 2);
        #pragma unroll
        for (int jf = 0; jf < 8; jf++) {
            int col = n0 + wn * 64 + jf * 8 + (lane & 3) * 2;
            float2 b2 = *reinterpret_cast<const float2*>(bias + col);
            float2 o0, o1;
            o0.x = acc[jf][0] + b2.x; o0.y = acc[jf][1] + b2.y;
            o1.x = acc[jf][2] + b2.x; o1.y = acc[jf][3] + b2.y;
            *reinterpret_cast<float2*>(Cout + (size_t)rbase * CC + col) = o0;
            *reinterpret_cast<float2*>(Cout + (size_t)(rbase + 8) * CC + col) = o1;
        }
    }
}

// ===================== fused topk + attention + tau_new =====================
// One block per (b,t) row. Loads the tau row into smem ONCE; does rowsum +
// top-4 (packed keys), sparse attention (warp = head), EMA signal, then
// scales the row from smem and patches the 4 selected entries.
__global__ __launch_bounds__(256) void attn_topk_fused(const float* __restrict__ tau,
                                                       float* __restrict__ out_tau) {
    const int row = blockIdx.x;
    const int tid = threadIdx.x;
    const int warp = tid >> 5, lane = tid & 31;   // warp == head
    const int b = row / TT;

    __shared__ float stau[TT];                    // 8 KB
    __shared__ unsigned long long sk[256 * 4];    // 8 KB
    __shared__ float red[256];
    __shared__ int   sidx[KSEL];
    __shared__ float sbias[KSEL];
    __shared__ float stval[KSEL];
    __shared__ float ssig[KSEL];
    __shared__ float sinv;

    // ---- load tau row + per-thread top4 + sum ----
    const float4* tin = reinterpret_cast<const float4*>(tau + (size_t)row * TT);
    unsigned long long k0 = 0, k1 = 0, k2 = 0, k3 = 0;
    float sum = 0.f;
    #pragma unroll
    for (int t = 0; t < 2; t++) {
        int i = tid + t * 256;                    // float4 index
        float4 v = tin[i];
        reinterpret_cast<float4*>(stau)[i] = v;
        float vv[4] = {v.x, v.y, v.z, v.w};
        #pragma unroll
        for (int j = 0; j < 4; j++) {
            sum += vv[j];
            int col = i * 4 + j;
            unsigned long long key =
                ((unsigned long long)__float_as_uint(vv[j]) << 32) | (unsigned)(0x7FFFFFFF - col);
            if (key > k3) {
                if (key > k0)      { k3 = k2; k2 = k1; k1 = k0; k0 = key; }
                else if (key > k1) { k3 = k2; k2 = k1; k1 = key; }
                else if (key > k2) { k3 = k2; k2 = key; }
                else               { k3 = key; }
            }
        }
    }
    sk[tid * 4 + 0] = k0; sk[tid * 4 + 1] = k1;
    sk[tid * 4 + 2] = k2; sk[tid * 4 + 3] = k3;
    red[tid] = sum;
    __syncthreads();

    for (int s = 128; s > 0; s >>= 1) {
        if (tid < s) {
            red[tid] += red[tid + s];
            unsigned long long a[4], bb[4], o[4];
            #pragma unroll
            for (int t = 0; t < 4; t++) { a[t] = sk[tid * 4 + t]; bb[t] = sk[(tid + s) * 4 + t]; }
            int ia = 0, ib = 0;
            #pragma unroll
            for (int t = 0; t < 4; t++) {
                if (a[ia] >= bb[ib]) o[t] = a[ia++];
                else                 o[t] = bb[ib++];
            }
            #pragma unroll
            for (int t = 0; t < 4; t++) sk[tid * 4 + t] = o[t];
        }
        __syncthreads();
    }
    if (tid < KSEL) {
        int id = 0x7FFFFFFF - (int)(sk[tid] & 0xFFFFFFFFu);
        float tv = stau[id];
        sidx[tid]  = id;
        stval[tid] = tv;
        sbias[tid] = GAMMA_F * logf(tv + 1e-8f);
        ssig[tid]  = 0.f;
    }
    __syncthreads();

    // ---- sparse attention ----
    const float* qp = g_qkv + (size_t)row * C3 + warp * DD;
    const float q0 = qp[lane], q1 = qp[lane + 32];

    float logit[KSEL];
    #pragma unroll
    for (int j = 0; j < KSEL; j++) {
        int s = sidx[j];
        const float* kp = g_qkv + (size_t)(b * TT + s) * C3 + CC + warp * DD;
        float p = q0 * kp[lane] + q1 * kp[lane + 32];
        #pragma unroll
        for (int o = 16; o > 0; o >>= 1) p += __shfl_xor_sync(0xffffffffu, p, o);
        logit[j] = p * 0.125f + sbias[j];
    }
    float m = fmaxf(fmaxf(logit[0], logit[1]), fmaxf(logit[2], logit[3]));
    float e[KSEL], se = 0.f;
    #pragma unroll
    for (int j = 0; j < KSEL; j++) { e[j] = expf(logit[j] - m); se += e[j]; }
    float inv = 1.f / se;
    float w[KSEL];
    #pragma unroll
    for (int j = 0; j < KSEL; j++) w[j] = e[j] * inv;

    float o0 = 0.f, o1 = 0.f;
    #pragma unroll
    for (int j = 0; j < KSEL; j++) {
        const float* vp = g_qkv + (size_t)(b * TT + sidx[j]) * C3 + 2 * CC + warp * DD;
        o0 = fmaf(w[j], vp[lane], o0);
        o1 = fmaf(w[j], vp[lane + 32], o1);
    }
    size_t obase = (size_t)row * KTOT + warp * DD;
    __half h0 = __float2half(o0);
    __half h1 = __float2half(o1);
    g_ao_h[obase + lane]      = h0;
    g_ao_h[obase + lane + 32] = h1;
    g_ao_l[obase + lane]      = __float2half(o0 - __half2float(h0));
    g_ao_l[obase + lane + 32] = __float2half(o1 - __half2float(h1));

    if (lane == 0) {
        #pragma unroll
        for (int j = 0; j < KSEL; j++) atomicAdd(&ssig[j], w[j] * (1.0f / HH));
    }
    __syncthreads();
    if (tid == 0) {
        float rs = red[0] * (1.0f - RHO_F);
        #pragma unroll
        for (int j = 0; j < KSEL; j++) { float s = ssig[j]; rs += s * s * s; }
        sinv = 1.f / (rs + 1e-8f);
    }
    __syncthreads();

    // ---- tau_new: scale from smem + patch ----
    const float f = (1.0f - RHO_F) * sinv;
    float4* tout = reinterpret_cast<float4*>(out_tau + (size_t)row * TT);
    #pragma unroll
    for (int t = 0; t < 2; t++) {
        int i = tid + t * 256;
        float4 v = reinterpret_cast<const float4*>(stau)[i];
        v.x = fminf(v.x * f, TAUCLIP);
        v.y = fminf(v.y * f, TAUCLIP);
        v.z = fminf(v.z * f, TAUCLIP);
        v.w = fminf(v.w * f, TAUCLIP);
        tout[i] = v;
    }
    __syncthreads();
    if (tid < KSEL) {
        float s = ssig[tid];
        float v = stval[tid] * (1.0f - RHO_F) + s * s * s;
        out_tau[(size_t)row * TT + sidx[tid]] = fminf(v * sinv, TAUCLIP);
    }
}

// ===================== launch ===============================================
extern "C" void kernel_launch(void* const* d_in, const int* in_sizes, int n_in,
                              void* d_out, int out_size) {
    const float* x     = (const float*)d_in[0];
    const float* tau   = (const float*)d_in[1];
    const float* Wqkv  = (const float*)d_in[2];
    const float* bqkv  = (const float*)d_in[3];
    const float* Wproj = (const float*)d_in[4];
    const float* bproj = (const float*)d_in[5];

    float* out_main = (float*)d_out;
    float* out_tau  = out_main + (size_t)NROW * CC;

    void *p_qkv, *p_xh, *p_xl, *p_wqt, *p_wpt, *p_aoh, *p_aol;
    cudaGetSymbolAddress(&p_qkv, g_qkv);
    cudaGetSymbolAddress(&p_xh, g_x_h);   cudaGetSymbolAddress(&p_xl, g_x_l);
    cudaGetSymbolAddress(&p_wqt, g_wqt);  cudaGetSymbolAddress(&p_wpt, g_wpt);
    cudaGetSymbolAddress(&p_aoh, g_ao_h); cudaGetSymbolAddress(&p_aol, g_ao_l);

    cudaFuncSetAttribute(qkv_gemm64, cudaFuncAttributeMaxDynamicSharedMemorySize, Q64_SMEM);
    cudaFuncSetAttribute(proj_gemm, cudaFuncAttributeMaxDynamicSharedMemorySize, PROJ_SMEM);

    // 1-3. operand prep
    convert_split_h<<<(NROW * KTOT / 4) / 256, 256>>>(x, (__half*)p_xh, (__half*)p_xl, NROW * KTOT / 4);
    transpose_half<<<dim3(C3 / 32, KTOT / 32), dim3(32, 8)>>>(Wqkv, (__half*)p_wqt, KTOT, C3);
    transpose_half<<<dim3(CC / 32, KTOT / 32), dim3(32, 8)>>>(Wproj, (__half*)p_wpt, KTOT, CC);

    // 4. QKV GEMM (K-chunk 64, 2-stage, swizzled)
    qkv_gemm64<<<dim3(12, NROW / 128), 256, Q64_SMEM>>>(
        (const __half*)p_xh, (const __half*)p_xl, (const __half*)p_wqt,
        bqkv, (float*)p_qkv);

    // 5. fused: topk + sparse attention + tau_new
    attn_topk_fused<<<NROW, 256>>>(tau, out_tau);

    // 6. proj GEMM (fp16 2-term) -> d_out
    proj_gemm<<<dim3(CC / 128, NROW / 64), 256, PROJ_SMEM>>>(
        (const __half*)p_aoh, (const __half*)p_aol, (const __half*)p_wpt,
        bproj, out_main);
}